// round 2
// baseline (speedup 1.0000x reference)
#include <cuda_runtime.h>
#include <cstddef>

// Problem constants
#define B_DIM 8
#define N_DIM 256
#define ROWS (B_DIM * N_DIM)   // 2048
#define F_NODE 64
#define F_EDGE 16
#define M_MSG 64
#define G3 192                 // 3 * F_NODE
#define OUT_DIM 128
#define PASSES 3
#define MAXDEG 256

// ---------------- scratch (device globals; no allocation) ----------------
__device__ int   g_cnt[ROWS];
__device__ int   g_nbr[ROWS][MAXDEG];                   // 2 MB
__device__ float g_E[ROWS][MAXDEG][M_MSG];              // 134 MB reserved, ~13 MB touched
__device__ float g_h[ROWS][F_NODE];
__device__ float g_P[ROWS][M_MSG];
__device__ float g_GH[ROWS][G3];
__device__ float g_part[128][OUT_DIM];

__device__ __forceinline__ float sigmoidf(float x) {
    return 1.0f / (1.0f + __expf(-x));
}

// ---------------- build: sparse edge list + per-edge message contribution ----------------
// grid 2048 blocks x 256 threads. Thread j tests edge (row, j); prefix-scan via ballot.
__global__ __launch_bounds__(256) void build_kernel(
    const float* __restrict__ edges, const float* __restrict__ nodes,
    const float* __restrict__ W_msg, const float* __restrict__ b_msg)
{
    int row = blockIdx.x;
    int t = threadIdx.x;                 // == candidate neighbour j
    const float* erow = edges + (size_t)row * N_DIM * F_EDGE;

    // adjacency[row][t] = sum of 16 non-negative floats; nonzero <=> edge exists
    const float4* e4 = reinterpret_cast<const float4*>(erow) + t * 4;
    float4 v0 = e4[0], v1 = e4[1], v2 = e4[2], v3 = e4[3];
    float s = ((v0.x + v0.y) + (v0.z + v0.w)) + ((v1.x + v1.y) + (v1.z + v1.w))
            + ((v2.x + v2.y) + (v2.z + v2.w)) + ((v3.x + v3.y) + (v3.z + v3.w));
    int flag = (s != 0.0f);

    unsigned bal = __ballot_sync(0xffffffffu, flag);
    int lane = t & 31, warp = t >> 5;
    __shared__ int wcnt[8];
    __shared__ int s_cnt;
    if (lane == 0) wcnt[warp] = __popc(bal);
    __syncthreads();
    int base = 0;
    #pragma unroll
    for (int w = 0; w < 8; w++) if (w < warp) base += wcnt[w];
    int slot = base + __popc(bal & ((1u << lane) - 1u));
    if (flag) g_nbr[row][slot] = t;
    if (t == 0) {
        int tot = 0;
        #pragma unroll
        for (int w = 0; w < 8; w++) tot += wcnt[w];
        s_cnt = tot;
        g_cnt[row] = tot;
    }
    // initialize h = nodes
    if (t < F_NODE) g_h[row][t] = nodes[(size_t)row * F_NODE + t];
    __syncthreads();

    // per-edge precompute: E[row][k][m] = b_msg[m] + e_ij . W_msg[64:80, m]
    int cnt = s_cnt;
    int m = t & 63;
    for (int k = t >> 6; k < cnt; k += 4) {
        int j = g_nbr[row][k];
        const float* e = erow + j * F_EDGE;
        float acc = b_msg[m];
        #pragma unroll
        for (int c = 0; c < F_EDGE; c++)
            acc = fmaf(e[c], W_msg[(F_NODE + c) * M_MSG + m], acc);
        g_E[row][k][m] = acc;
    }
}

// ---------------- per pass, phase 1: P = h @ W_msg[:64] ; GH = h @ W_h + b_h ----------------
__global__ __launch_bounds__(256) void pgh_kernel(
    const float* __restrict__ W_msg, const float* __restrict__ W_h,
    const float* __restrict__ b_h)
{
    int row = blockIdx.x;
    int t = threadIdx.x;
    __shared__ float sh[F_NODE];
    if (t < F_NODE) sh[t] = g_h[row][t];
    __syncthreads();
    if (t < F_NODE) {
        float acc = 0.0f;
        #pragma unroll
        for (int c = 0; c < F_NODE; c++)
            acc = fmaf(sh[c], W_msg[c * M_MSG + t], acc);
        g_P[row][t] = acc;
    } else {
        int g = t - F_NODE;              // 0..191
        float acc = b_h[g];
        #pragma unroll
        for (int c = 0; c < F_NODE; c++)
            acc = fmaf(sh[c], W_h[c * G3 + g], acc);
        g_GH[row][g] = acc;
    }
}

// ---------------- per pass, phase 2: messages + GRU update (fused) ----------------
__global__ __launch_bounds__(192) void msggru_kernel(
    const float* __restrict__ W_i, const float* __restrict__ b_i)
{
    int row = blockIdx.x;
    int t = threadIdx.x;                 // 0..191
    int b = row >> 8;
    int cnt = g_cnt[row];

    __shared__ float s_part[3][M_MSG];
    __shared__ float s_msg[M_MSG];
    __shared__ float s_rz[2 * F_NODE];
    __shared__ float s_inn[F_NODE];
    __shared__ float s_hn[F_NODE];

    int grp = t >> 6, m = t & 63;
    float acc = 0.0f;
    for (int k = grp; k < cnt; k += 3) {
        int j = g_nbr[row][k];
        float v = g_P[(b << 8) + j][m] + g_E[row][k][m];
        acc += fmaxf(v, 0.0f);
    }
    s_part[grp][m] = acc;
    __syncthreads();
    if (t < M_MSG) s_msg[t] = s_part[0][t] + s_part[1][t] + s_part[2][t];
    __syncthreads();

    // gi = msg @ W_i + b_i (each thread one of 192 columns)
    float gi = b_i[t];
    #pragma unroll
    for (int c = 0; c < M_MSG; c++)
        gi = fmaf(s_msg[c], W_i[c * G3 + t], gi);
    float gh = g_GH[row][t];

    if (t < 128) s_rz[t] = gi + gh;
    else { s_inn[t - 128] = gi; s_hn[t - 128] = gh; }
    __syncthreads();

    if (t < F_NODE && cnt > 0) {
        float r  = sigmoidf(s_rz[t]);
        float z  = sigmoidf(s_rz[F_NODE + t]);
        float ng = tanhf(s_inn[t] + r * s_hn[t]);
        float ho = g_h[row][t];
        g_h[row][t] = (1.0f - z) * ng + z * ho;
    }
}

// ---------------- readout: partial sums over 16-node chunks ----------------
__global__ __launch_bounds__(128) void readout_partial(
    const float* __restrict__ nodes,
    const float* __restrict__ W_g, const float* __restrict__ b_g,
    const float* __restrict__ W_e, const float* __restrict__ b_e)
{
    int blk = blockIdx.x;                // 0..127
    int b = blk >> 4, chunk = blk & 15;
    int o = threadIdx.x;                 // 0..127
    __shared__ float sh_h[F_NODE];
    __shared__ float sh_x[F_NODE];
    float acc = 0.0f;

    for (int ii = 0; ii < 16; ii++) {
        int row = (b << 8) + chunk * 16 + ii;
        __syncthreads();
        if (o < F_NODE) sh_h[o] = g_h[row][o];
        else            sh_x[o - F_NODE] = nodes[(size_t)row * F_NODE + (o - F_NODE)];
        __syncthreads();
        if (g_cnt[row] > 0) {
            float gacc = b_g[o];
            float eacc = b_e[o];
            #pragma unroll
            for (int c = 0; c < F_NODE; c++) {
                gacc = fmaf(sh_h[c], W_g[c * OUT_DIM + o], gacc);
                eacc = fmaf(sh_h[c], W_e[c * OUT_DIM + o], eacc);
            }
            #pragma unroll
            for (int c = 0; c < F_NODE; c++)
                gacc = fmaf(sh_x[c], W_g[(F_NODE + c) * OUT_DIM + o], gacc);
            acc += sigmoidf(gacc) * eacc;
        }
    }
    g_part[blk][o] = acc;
}

__global__ __launch_bounds__(128) void readout_final(float* __restrict__ out)
{
    int b = blockIdx.x;                  // 0..7
    int o = threadIdx.x;                 // 0..127
    float acc = 0.0f;
    #pragma unroll
    for (int c = 0; c < 16; c++) acc += g_part[b * 16 + c][o];
    out[b * OUT_DIM + o] = acc;
}

// ---------------- launch ----------------
extern "C" void kernel_launch(void* const* d_in, const int* in_sizes, int n_in,
                              void* d_out, int out_size)
{
    const float* nodes = (const float*)d_in[0];
    const float* edges = (const float*)d_in[1];
    const float* W_msg = (const float*)d_in[2];
    const float* b_msg = (const float*)d_in[3];
    const float* W_i   = (const float*)d_in[4];
    const float* W_h   = (const float*)d_in[5];
    const float* b_i   = (const float*)d_in[6];
    const float* b_h   = (const float*)d_in[7];
    const float* W_g   = (const float*)d_in[8];
    const float* b_g   = (const float*)d_in[9];
    const float* W_e   = (const float*)d_in[10];
    const float* b_e   = (const float*)d_in[11];
    float* out = (float*)d_out;

    build_kernel<<<ROWS, 256>>>(edges, nodes, W_msg, b_msg);
    for (int p = 0; p < PASSES; p++) {
        pgh_kernel<<<ROWS, 256>>>(W_msg, W_h, b_h);
        msggru_kernel<<<ROWS, 192>>>(W_i, b_i);
    }
    readout_partial<<<128, 128>>>(nodes, W_g, b_g, W_e, b_e);
    readout_final<<<8, 128>>>(out);
}

// round 3
// speedup vs baseline: 1.1286x; 1.1286x over previous
#include <cuda_runtime.h>
#include <cstddef>

// Problem constants
#define B_DIM 8
#define N_DIM 256
#define ROWS (B_DIM * N_DIM)   // 2048
#define F_NODE 64
#define F_EDGE 16
#define M_MSG 64
#define G3 192                 // 3 * F_NODE
#define OUT_DIM 128
#define PASSES 3
#define MAXDEG 256

typedef unsigned long long ull;

// ---------------- scratch (device globals; no allocation) ----------------
__device__ int   g_cnt[ROWS];
__device__ int   g_nbr[ROWS][MAXDEG];
__device__ __align__(16) float g_E[ROWS][MAXDEG][M_MSG];   // per-edge precomputed bias+edge part
__device__ __align__(16) float g_h[ROWS][F_NODE];
__device__ __align__(16) float g_P[ROWS][M_MSG];
__device__ __align__(16) float g_GH[ROWS][G3];
__device__ float g_part[128][OUT_DIM];

__device__ __forceinline__ float sigmoidf(float x) {
    return 1.0f / (1.0f + __expf(-x));
}

// packed f32x2 helpers (sm_103a FFMA2 path)
__device__ __forceinline__ ull pack2(float lo, float hi) {
    ull r;
    asm("mov.b64 %0, {%1, %2};" : "=l"(r) : "f"(lo), "f"(hi));
    return r;
}
__device__ __forceinline__ void unpack2(ull v, float& lo, float& hi) {
    asm("mov.b64 {%0, %1}, %2;" : "=f"(lo), "=f"(hi) : "l"(v));
}
__device__ __forceinline__ ull fma2(ull a, ull b, ull c) {
    ull d;
    asm("fma.rn.f32x2 %0, %1, %2, %3;" : "=l"(d) : "l"(a), "l"(b), "l"(c));
    return d;
}

// ---------------- build: sparse edge list + per-edge message contribution ----------------
// grid 2048 x 256. Thread j tests edge (row, j); ballot prefix-scan; then per-edge
// E[row][k][:] = b_msg + e_ij @ W_msg[64:80,:]  computed with packed f32x2.
__global__ __launch_bounds__(256) void build_kernel(
    const float* __restrict__ edges, const float* __restrict__ nodes,
    const float* __restrict__ W_msg, const float* __restrict__ b_msg)
{
    int row = blockIdx.x;
    int t = threadIdx.x;
    const float* erow = edges + (size_t)row * N_DIM * F_EDGE;

    __shared__ int wcnt[8];
    __shared__ int s_cnt;
    __shared__ int snbr[256];
    __shared__ ull s_w2[F_EDGE][32];   // packed edge-weight pairs
    __shared__ ull s_b2[32];

    // adjacency sum (16 non-negative floats): nonzero <=> edge exists
    const float4* e4 = reinterpret_cast<const float4*>(erow) + t * 4;
    float4 v0 = e4[0], v1 = e4[1], v2 = e4[2], v3 = e4[3];
    float s = ((v0.x + v0.y) + (v0.z + v0.w)) + ((v1.x + v1.y) + (v1.z + v1.w))
            + ((v2.x + v2.y) + (v2.z + v2.w)) + ((v3.x + v3.y) + (v3.z + v3.w));
    int flag = (s != 0.0f);

    unsigned bal = __ballot_sync(0xffffffffu, flag);
    int lane = t & 31, warp = t >> 5;
    if (lane == 0) wcnt[warp] = __popc(bal);

    // stage packed weights/bias while scan settles
    for (int i = t; i < F_EDGE * 32; i += 256) {
        int c = i >> 5, m2 = i & 31;
        s_w2[c][m2] = pack2(W_msg[(F_NODE + c) * M_MSG + 2 * m2],
                            W_msg[(F_NODE + c) * M_MSG + 2 * m2 + 1]);
    }
    if (t < 32) s_b2[t] = pack2(b_msg[2 * t], b_msg[2 * t + 1]);
    __syncthreads();

    int base = 0;
    #pragma unroll
    for (int w = 0; w < 8; w++) if (w < warp) base += wcnt[w];
    int slot = base + __popc(bal & ((1u << lane) - 1u));
    if (flag) { snbr[slot] = t; g_nbr[row][slot] = t; }
    if (t == 0) {
        int tot = 0;
        #pragma unroll
        for (int w = 0; w < 8; w++) tot += wcnt[w];
        s_cnt = tot;
        g_cnt[row] = tot;
    }
    if (t < F_NODE) g_h[row][t] = nodes[(size_t)row * F_NODE + t];
    __syncthreads();

    int cnt = s_cnt;
    int grp = t >> 5, m2 = t & 31;       // 8 groups of 32 threads, 2 outputs each
    for (int k = grp; k < cnt; k += 8) {
        int j = snbr[k];
        const float4* ep = reinterpret_cast<const float4*>(erow + j * F_EDGE);
        float4 a = ep[0], b4 = ep[1], c4 = ep[2], d4 = ep[3];
        float ev[16] = {a.x,a.y,a.z,a.w, b4.x,b4.y,b4.z,b4.w,
                        c4.x,c4.y,c4.z,c4.w, d4.x,d4.y,d4.z,d4.w};
        ull acc = s_b2[m2];
        #pragma unroll
        for (int c = 0; c < F_EDGE; c++)
            acc = fma2(pack2(ev[c], ev[c]), s_w2[c][m2], acc);
        ull* dst = reinterpret_cast<ull*>(&g_E[row][k][0]);
        dst[m2] = acc;
    }
}

// ---------------- phase 1: P = h @ W_msg[:64] ; GH = h @ W_h + b_h ----------------
// grid 128 x 256, 16 rows/block. Weights staged in smem once, rows packed in f32x2 pairs.
__global__ __launch_bounds__(256) void pgh_kernel(
    const float* __restrict__ W_msg, const float* __restrict__ W_h,
    const float* __restrict__ b_h)
{
    extern __shared__ char smem[];
    float* wS = reinterpret_cast<float*>(smem);                 // [64][256]
    ull*   h2 = reinterpret_cast<ull*>(smem + 65536);           // [64][8] row pairs

    int row0 = blockIdx.x * 16;
    int t = threadIdx.x;

    // stage weights: col t, all 64 input channels
    for (int c = 0; c < F_NODE; c++)
        wS[c * 256 + t] = (t < F_NODE) ? W_msg[c * M_MSG + t]
                                       : W_h[c * G3 + (t - F_NODE)];
    // stage h as packed row-pairs: h2[c][p] = {h[2p][c], h[2p+1][c]}
    for (int i = t; i < F_NODE * 8; i += 256) {
        int c = i >> 3, p = i & 7;
        h2[c * 8 + p] = pack2(g_h[row0 + 2 * p][c], g_h[row0 + 2 * p + 1][c]);
    }
    __syncthreads();

    float bias = (t < F_NODE) ? 0.0f : b_h[t - F_NODE];
    ull acc[8];
    #pragma unroll
    for (int p = 0; p < 8; p++) acc[p] = pack2(bias, bias);

    #pragma unroll 4
    for (int c = 0; c < F_NODE; c++) {
        float wv = wS[c * 256 + t];
        ull w2 = pack2(wv, wv);
        const ulonglong2* hq = reinterpret_cast<const ulonglong2*>(&h2[c * 8]);
        ulonglong2 q0 = hq[0], q1 = hq[1], q2 = hq[2], q3 = hq[3];
        acc[0] = fma2(q0.x, w2, acc[0]); acc[1] = fma2(q0.y, w2, acc[1]);
        acc[2] = fma2(q1.x, w2, acc[2]); acc[3] = fma2(q1.y, w2, acc[3]);
        acc[4] = fma2(q2.x, w2, acc[4]); acc[5] = fma2(q2.y, w2, acc[5]);
        acc[6] = fma2(q3.x, w2, acc[6]); acc[7] = fma2(q3.y, w2, acc[7]);
    }

    #pragma unroll
    for (int p = 0; p < 8; p++) {
        float lo, hi; unpack2(acc[p], lo, hi);
        if (t < F_NODE) {
            g_P[row0 + 2 * p][t] = lo;
            g_P[row0 + 2 * p + 1][t] = hi;
        } else {
            g_GH[row0 + 2 * p][t - F_NODE] = lo;
            g_GH[row0 + 2 * p + 1][t - F_NODE] = hi;
        }
    }
}

// ---------------- phase 2: messages + GRU update, 8 rows/block ----------------
// grid 256 x 192. W_i staged once; gathers for all 8 rows, then packed-gi, then GRU.
__global__ __launch_bounds__(192) void msggru_kernel(
    const float* __restrict__ W_i, const float* __restrict__ b_i)
{
    extern __shared__ char smem[];
    float* wiS     = reinterpret_cast<float*>(smem);                  // [64][192]
    ull*   msg2    = reinterpret_cast<ull*>(smem + 49152);            // [64][4] row pairs
    float* part3   = reinterpret_cast<float*>(smem + 51200);          // [8][3][64]
    float* s_gi    = reinterpret_cast<float*>(smem + 57344);          // [8][200]
    float* s_gh    = reinterpret_cast<float*>(smem + 63744);          // [8][200]
    float* s_bi    = reinterpret_cast<float*>(smem + 70144);          // [192]
    int*   s_cnt   = reinterpret_cast<int*>(smem + 70912);            // [8]

    int row0 = blockIdx.x * 8;
    int bbase = (row0 >> 8) << 8;   // batch base row
    int t = threadIdx.x;

    for (int c = 0; c < M_MSG; c++)
        wiS[c * 192 + t] = W_i[c * G3 + t];
    s_bi[t] = b_i[t];
    if (t < 8) s_cnt[t] = g_cnt[row0 + t];
    __syncthreads();

    // gather partial message sums for all 8 rows (3 groups of 64 over edges)
    int grp = t >> 6, m = t & 63;
    for (int r = 0; r < 8; r++) {
        int row = row0 + r;
        int cnt = s_cnt[r];
        float acc = 0.0f;
        for (int k = grp; k < cnt; k += 3) {
            int j = g_nbr[row][k];
            float v = g_P[bbase + j][m] + g_E[row][k][m];
            acc += fmaxf(v, 0.0f);
        }
        part3[(r * 3 + grp) * 64 + m] = acc;
    }
    __syncthreads();

    // reduce + pack messages into row pairs: msg2[c][p] = {msg[2p][c], msg[2p+1][c]}
    for (int i = t; i < M_MSG * 4; i += 192) {
        int c = i >> 2, p = i & 3;
        int ra = 2 * p, rb = 2 * p + 1;
        float lo = part3[(ra * 3 + 0) * 64 + c] + part3[(ra * 3 + 1) * 64 + c] + part3[(ra * 3 + 2) * 64 + c];
        float hi = part3[(rb * 3 + 0) * 64 + c] + part3[(rb * 3 + 1) * 64 + c] + part3[(rb * 3 + 2) * 64 + c];
        msg2[c * 4 + p] = pack2(lo, hi);
    }
    __syncthreads();

    // gi = msg @ W_i + b_i for 8 rows (4 packed pairs)
    float bi = s_bi[t];
    ull gi2[4];
    #pragma unroll
    for (int p = 0; p < 4; p++) gi2[p] = pack2(bi, bi);
    #pragma unroll 4
    for (int c = 0; c < M_MSG; c++) {
        float wv = wiS[c * 192 + t];
        ull w2 = pack2(wv, wv);
        const ulonglong2* mq = reinterpret_cast<const ulonglong2*>(&msg2[c * 4]);
        ulonglong2 q0 = mq[0], q1 = mq[1];
        gi2[0] = fma2(q0.x, w2, gi2[0]); gi2[1] = fma2(q0.y, w2, gi2[1]);
        gi2[2] = fma2(q1.x, w2, gi2[2]); gi2[3] = fma2(q1.y, w2, gi2[3]);
    }

    // spill gi/gh per row
    #pragma unroll
    for (int p = 0; p < 4; p++) {
        float lo, hi; unpack2(gi2[p], lo, hi);
        s_gi[(2 * p) * 200 + t] = lo;
        s_gi[(2 * p + 1) * 200 + t] = hi;
    }
    #pragma unroll
    for (int r = 0; r < 8; r++)
        s_gh[r * 200 + t] = g_GH[row0 + r][t];
    __syncthreads();

    // GRU epilogue: group grp handles rows {grp, grp+3, grp+6}
    int i = t & 63;
    for (int r = grp; r < 8; r += 3) {
        if (s_cnt[r] > 0) {
            float ir  = s_gi[r * 200 + i]       + s_gh[r * 200 + i];
            float iz  = s_gi[r * 200 + 64 + i]  + s_gh[r * 200 + 64 + i];
            float inn = s_gi[r * 200 + 128 + i];
            float hn  = s_gh[r * 200 + 128 + i];
            float rg = sigmoidf(ir);
            float z  = sigmoidf(iz);
            float ng = tanhf(inn + rg * hn);
            float ho = g_h[row0 + r][i];
            g_h[row0 + r][i] = (1.0f - z) * ng + z * ho;
        }
    }
}

// ---------------- readout: gated sum, 16 rows/block packed in f32x2 ----------------
__global__ __launch_bounds__(128) void readout_partial(
    const float* __restrict__ nodes,
    const float* __restrict__ W_g, const float* __restrict__ b_g,
    const float* __restrict__ W_e, const float* __restrict__ b_e)
{
    extern __shared__ char smem[];
    float* wgS = reinterpret_cast<float*>(smem);            // [128][128]
    float* weS = reinterpret_cast<float*>(smem + 65536);    // [64][128]
    ull*   hx2 = reinterpret_cast<ull*>(smem + 98304);      // [128][8]
    int*  s_cn = reinterpret_cast<int*>(smem + 106496);     // [16]

    int row0 = blockIdx.x * 16;
    int t = threadIdx.x;   // output column o

    for (int c = 0; c < 2 * F_NODE; c++)
        wgS[c * 128 + t] = W_g[c * OUT_DIM + t];
    for (int c = 0; c < F_NODE; c++)
        weS[c * 128 + t] = W_e[c * OUT_DIM + t];
    for (int i = t; i < 128 * 8; i += 128) {
        int c = i >> 3, p = i & 7;
        int ra = row0 + 2 * p, rb = ra + 1;
        float lo = (c < F_NODE) ? g_h[ra][c] : nodes[(size_t)ra * F_NODE + (c - F_NODE)];
        float hi = (c < F_NODE) ? g_h[rb][c] : nodes[(size_t)rb * F_NODE + (c - F_NODE)];
        hx2[c * 8 + p] = pack2(lo, hi);
    }
    if (t < 16) s_cn[t] = g_cnt[row0 + t];
    __syncthreads();

    float bg = b_g[t], be = b_e[t];
    ull accg[8], acce[8];
    #pragma unroll
    for (int p = 0; p < 8; p++) { accg[p] = pack2(bg, bg); acce[p] = pack2(be, be); }

    // c < 64: both gate (h part) and emb
    #pragma unroll 2
    for (int c = 0; c < F_NODE; c++) {
        ull wg2 = pack2(wgS[c * 128 + t], wgS[c * 128 + t]);
        ull we2 = pack2(weS[c * 128 + t], weS[c * 128 + t]);
        const ulonglong2* hq = reinterpret_cast<const ulonglong2*>(&hx2[c * 8]);
        ulonglong2 q0 = hq[0], q1 = hq[1], q2 = hq[2], q3 = hq[3];
        accg[0] = fma2(q0.x, wg2, accg[0]); acce[0] = fma2(q0.x, we2, acce[0]);
        accg[1] = fma2(q0.y, wg2, accg[1]); acce[1] = fma2(q0.y, we2, acce[1]);
        accg[2] = fma2(q1.x, wg2, accg[2]); acce[2] = fma2(q1.x, we2, acce[2]);
        accg[3] = fma2(q1.y, wg2, accg[3]); acce[3] = fma2(q1.y, we2, acce[3]);
        accg[4] = fma2(q2.x, wg2, accg[4]); acce[4] = fma2(q2.x, we2, acce[4]);
        accg[5] = fma2(q2.y, wg2, accg[5]); acce[5] = fma2(q2.y, we2, acce[5]);
        accg[6] = fma2(q3.x, wg2, accg[6]); acce[6] = fma2(q3.x, we2, acce[6]);
        accg[7] = fma2(q3.y, wg2, accg[7]); acce[7] = fma2(q3.y, we2, acce[7]);
    }
    // c >= 64: gate only (x part)
    #pragma unroll 2
    for (int c = F_NODE; c < 2 * F_NODE; c++) {
        ull wg2 = pack2(wgS[c * 128 + t], wgS[c * 128 + t]);
        const ulonglong2* hq = reinterpret_cast<const ulonglong2*>(&hx2[c * 8]);
        ulonglong2 q0 = hq[0], q1 = hq[1], q2 = hq[2], q3 = hq[3];
        accg[0] = fma2(q0.x, wg2, accg[0]); accg[1] = fma2(q0.y, wg2, accg[1]);
        accg[2] = fma2(q1.x, wg2, accg[2]); accg[3] = fma2(q1.y, wg2, accg[3]);
        accg[4] = fma2(q2.x, wg2, accg[4]); accg[5] = fma2(q2.y, wg2, accg[5]);
        accg[6] = fma2(q3.x, wg2, accg[6]); accg[7] = fma2(q3.y, wg2, accg[7]);
    }

    float total = 0.0f;
    #pragma unroll
    for (int p = 0; p < 8; p++) {
        float glo, ghi, elo, ehi;
        unpack2(accg[p], glo, ghi);
        unpack2(acce[p], elo, ehi);
        if (s_cn[2 * p]     > 0) total += sigmoidf(glo) * elo;
        if (s_cn[2 * p + 1] > 0) total += sigmoidf(ghi) * ehi;
    }
    g_part[blockIdx.x][t] = total;
}

__global__ __launch_bounds__(128) void readout_final(float* __restrict__ out)
{
    int b = blockIdx.x;
    int o = threadIdx.x;
    float acc = 0.0f;
    #pragma unroll
    for (int c = 0; c < 16; c++) acc += g_part[b * 16 + c][o];
    out[b * OUT_DIM + o] = acc;
}

// ---------------- launch ----------------
extern "C" void kernel_launch(void* const* d_in, const int* in_sizes, int n_in,
                              void* d_out, int out_size)
{
    const float* nodes = (const float*)d_in[0];
    const float* edges = (const float*)d_in[1];
    const float* W_msg = (const float*)d_in[2];
    const float* b_msg = (const float*)d_in[3];
    const float* W_i   = (const float*)d_in[4];
    const float* W_h   = (const float*)d_in[5];
    const float* b_i   = (const float*)d_in[6];
    const float* b_h   = (const float*)d_in[7];
    const float* W_g   = (const float*)d_in[8];
    const float* b_g   = (const float*)d_in[9];
    const float* W_e   = (const float*)d_in[10];
    const float* b_e   = (const float*)d_in[11];
    float* out = (float*)d_out;

    const int PGH_SMEM  = 65536 + 4096;          // wS + h2
    const int MSG_SMEM  = 70944;                 // wiS + msg2 + part3 + gi/gh + bi + cnt
    const int RO_SMEM   = 106496 + 64;           // wgS + weS + hx2 + cnt

    cudaFuncSetAttribute(pgh_kernel,      cudaFuncAttributeMaxDynamicSharedMemorySize, PGH_SMEM);
    cudaFuncSetAttribute(msggru_kernel,   cudaFuncAttributeMaxDynamicSharedMemorySize, MSG_SMEM);
    cudaFuncSetAttribute(readout_partial, cudaFuncAttributeMaxDynamicSharedMemorySize, RO_SMEM);

    build_kernel<<<ROWS, 256>>>(edges, nodes, W_msg, b_msg);
    for (int p = 0; p < PASSES; p++) {
        pgh_kernel<<<128, 256, PGH_SMEM>>>(W_msg, W_h, b_h);
        msggru_kernel<<<256, 192, MSG_SMEM>>>(W_i, b_i);
    }
    readout_partial<<<128, 128, RO_SMEM>>>(nodes, W_g, b_g, W_e, b_e);
    readout_final<<<8, 128>>>(out);
}